// round 13
// baseline (speedup 1.0000x reference)
#include <cuda_runtime.h>
#include <cstdint>

// ============================================================================
// QuantLinear: y = x @ (scales*q - zeros) + bias        (sm_100 portable path)
//   x:[32,4096] f32, qweight:[512,11008] i32 (8 nibbles/word along K),
//   scales/zeros/bias:[11008] f32, out:[32,11008] f32
//
// INT8 tensor-core path, fixed scale c = 2^-12:  x ~= c*(256*h + l), h,l s8.
//   prep:  128 blocks: quantize+permute (0,2,4,6,1,3,5,7) within groups of 8,
//          rows 0-31 = h, rows 32-63 = l; partial row sums; zeroes out[].
//   gemm:  persistent-balanced 2752 units over 296 CTAs. 4-stage cp.async.
//          mma.m16n8k32.s32.s8.s8. Warp split (mg,ng): mg = hi/lo rows
//          (8 LDSM/warp/unit), ng = 32-col group. Column pairing
//          g(j,f) = (j&2)*8 + 2f + (j&1) makes each thread's two slice
//          words adjacent -> Q loads are 16 full-width LDS.64 per warp/unit.
//          Epilogue: hi warps add s*256c*Dh [+ b - S*z], lo warps s*c*Dl.
// ============================================================================

#define KTOT   4096
#define NTOT   11008
#define MTOK   32
#define TILE_N 128
#define TILE_K 128
#define NCHUNK 32
#define NTILES 86
#define UNITS  (NTILES * NCHUNK)  // 2752
#define GRID   296                // 2 x 148 SMs
#define THREADS 256
#define STAGES 4

#define CQ (1.0f / 4096.0f)       // fixed quant scale

#define STAGE_BYTES 16384         // A 8192 (64 rows x 128B) + Q 8192
#define SM_S (STAGES * STAGE_BYTES)
#define SMEM_TOTAL (SM_S + 128)   // + S[32]

#define OUTN (MTOK * NTOT)

__device__ __align__(16) int8_t g_A[64 * KTOT];
__device__ float g_Spart[128];    // 4 partials per token

// ---------------------------------------------------------------------------
__device__ __forceinline__ uint32_t smem_u32(const void* p) {
    uint32_t a;
    asm("{ .reg .u64 t; cvta.to.shared.u64 t, %1; cvt.u32.u64 %0, t; }"
        : "=r"(a) : "l"(p));
    return a;
}

#define CP16(dst, src) \
    asm volatile("cp.async.cg.shared.global [%0], [%1], 16;" :: "r"(dst), "l"(src))
#define CP_COMMIT() asm volatile("cp.async.commit_group;" ::: "memory")

__device__ __forceinline__ void imma16832(int* d, const uint32_t* a,
                                          uint32_t b0, uint32_t b1) {
    asm volatile(
        "mma.sync.aligned.m16n8k32.row.col.s32.s8.s8.s32 "
        "{%0,%1,%2,%3}, {%4,%5,%6,%7}, {%8,%9}, {%0,%1,%2,%3};"
        : "+r"(d[0]), "+r"(d[1]), "+r"(d[2]), "+r"(d[3])
        : "r"(a[0]), "r"(a[1]), "r"(a[2]), "r"(a[3]), "r"(b0), "r"(b1));
}

__device__ __forceinline__ void ldmx4(uint32_t* a, uint32_t addr) {
    asm volatile("ldmatrix.sync.aligned.m8n8.x4.shared.b16 {%0,%1,%2,%3}, [%4];"
                 : "=r"(a[0]), "=r"(a[1]), "=r"(a[2]), "=r"(a[3]) : "r"(addr));
}

#define LDS64(vx, vy, addr) \
    asm volatile("ld.shared.v2.b32 {%0,%1}, [%2];" : "=r"(vx), "=r"(vy) : "r"(addr))

// ---------------------------------------------------------------------------
// prep: 128 blocks (32 tokens x 4 slices) x 128 threads; thread = one group
// of 8 k-values. Fixed c = 2^-12 -> no block-wide reductions.
// ---------------------------------------------------------------------------
__global__ void __launch_bounds__(128, 4) prep_kernel(const float* __restrict__ x,
                                                      float* __restrict__ out) {
    int t = blockIdx.x >> 2, sl = blockIdx.x & 3, tid = threadIdx.x;
    int k0 = sl * 1024 + tid * 8;
    const float4* p = (const float4*)(x + (size_t)t * KTOT + k0);
    float4 va = p[0], vb = p[1];
    float v[8] = {va.x, va.y, va.z, va.w, vb.x, vb.y, vb.z, vb.w};

    int hq[8], lq[8];
    int hsum = 0, lsum = 0;
    #pragma unroll
    for (int i = 0; i < 8; i++) {
        float hf = rintf(v[i] * 16.0f);            // x / (256*c), 256c = 1/16
        int h = (int)hf;
        float r = fmaf(hf, -0.0625f, v[i]);        // x - 256c*h
        int l = (int)rintf(r * 4096.0f);           // r / c
        if (l == 128) { l = -128; h += 1; }
        hsum += h; lsum += l;
        int pp = (i >> 1) + ((i & 1) << 2);        // (0,2,4,6,1,3,5,7)
        hq[pp] = h; lq[pp] = l;
    }
    uint2 hw, lw;
    hw.x = (hq[0] & 0xFF) | ((hq[1] & 0xFF) << 8) | ((hq[2] & 0xFF) << 16) | ((hq[3] & 0xFF) << 24);
    hw.y = (hq[4] & 0xFF) | ((hq[5] & 0xFF) << 8) | ((hq[6] & 0xFF) << 16) | ((hq[7] & 0xFF) << 24);
    lw.x = (lq[0] & 0xFF) | ((lq[1] & 0xFF) << 8) | ((lq[2] & 0xFF) << 16) | ((lq[3] & 0xFF) << 24);
    lw.y = (lq[4] & 0xFF) | ((lq[5] & 0xFF) << 8) | ((lq[6] & 0xFF) << 16) | ((lq[7] & 0xFF) << 24);
    *(uint2*)(g_A + (size_t)t * KTOT + k0) = hw;
    *(uint2*)(g_A + (size_t)(t + 32) * KTOT + k0) = lw;

    // zero out[] (float4 strided over all 16384 prep threads)
    int gtid = blockIdx.x * 128 + tid;
    const float4 z4 = {0.f, 0.f, 0.f, 0.f};
    for (int i = gtid; i < OUTN / 4; i += 128 * 128)
        ((float4*)out)[i] = z4;

    // partial row sum: S_part = c*(256*H + L)
    float acc = 256.0f * (float)hsum + (float)lsum;
    #pragma unroll
    for (int off = 16; off; off >>= 1) acc += __shfl_down_sync(0xFFFFFFFFu, acc, off);
    __shared__ float red[4];
    if ((tid & 31) == 0) red[tid >> 5] = acc;
    __syncthreads();
    if (tid == 0)
        g_Spart[blockIdx.x] = CQ * (red[0] + red[1] + red[2] + red[3]);
}

// ---------------------------------------------------------------------------
// gemm (persistent balanced, INT8, M-split warps, paired-column Q loads)
// ---------------------------------------------------------------------------
__device__ __forceinline__ void issue_unit(uint32_t sb, int tid, int u, int slot,
                                           const int* __restrict__ qw) {
    int nt = u >> 5, cg = u & 31;
    int n0 = nt * TILE_N;
    uint32_t stage = sb + (uint32_t)slot * STAGE_BYTES;
    // A: 64 rows x 8 segs of 16B (swizzled), 512 segs
    #pragma unroll
    for (int i = 0; i < 2; i++) {
        int seg = tid + i * 256;
        int r = seg >> 3, cc = seg & 7;
        uint32_t dst = stage + r * 128 + (((uint32_t)cc ^ (uint32_t)(r & 7)) << 4);
        const char* src = (const char*)g_A + (size_t)r * KTOT + (size_t)cg * TILE_K + cc * 16;
        CP16(dst, src);
    }
    // Q: 16 kwords x 32 segs of 16B (layout [kw][col], preserved)
    #pragma unroll
    for (int i = 0; i < 2; i++) {
        int seg = tid + i * 256;
        int kw = seg >> 5, ns = seg & 31;
        uint32_t dst = stage + 8192 + kw * 512 + ns * 16;
        const char* src = (const char*)qw + ((size_t)(cg * 16 + kw) * NTOT + n0) * 4 + ns * 16;
        CP16(dst, src);
    }
    CP_COMMIT();
}

__global__ void __launch_bounds__(THREADS, 2) gemm_kernel(
    const int* __restrict__ qw, const float* __restrict__ scales,
    const float* __restrict__ zeros, const float* __restrict__ bias,
    float* __restrict__ out) {
    extern __shared__ __align__(1024) char smem[];
    uint32_t sb = smem_u32(smem);
    int tid = threadIdx.x, wid = tid >> 5, lane = tid & 31;
    float* S_sm = (float*)(smem + SM_S);

    int u0 = (int)(((long long)blockIdx.x * UNITS) / GRID);
    int u1 = (int)(((long long)(blockIdx.x + 1) * UNITS) / GRID);

    if (tid < 32)
        S_sm[tid] = g_Spart[tid * 4] + g_Spart[tid * 4 + 1] +
                    g_Spart[tid * 4 + 2] + g_Spart[tid * 4 + 3];

    if (u0 + 0 < u1) issue_unit(sb, tid, u0 + 0, 0, qw);
    if (u0 + 1 < u1) issue_unit(sb, tid, u0 + 1, 1, qw);
    if (u0 + 2 < u1) issue_unit(sb, tid, u0 + 2, 2, qw);

    const int mg = wid & 1;              // 0 = hi rows 0-31, 1 = lo rows 32-63
    const int ng = wid >> 1;             // col group of 32
    const int lrow = lane & 15;
    const int lcb  = lane >> 4;
    const int j4   = lane & 3;
    const int nrow = lane >> 2;
    const uint32_t sh = (uint32_t)((j4 & 1) * 4);
    const int tg2 = j4 >> 1;

    int acc[2][4][4];
    #pragma unroll
    for (int mt = 0; mt < 2; mt++)
        #pragma unroll
        for (int j = 0; j < 4; j++)
            #pragma unroll
            for (int i = 0; i < 4; i++) acc[mt][j][i] = 0;

    int seg_nt = u0 >> 5;
    bool seg_first = ((u0 & 31) == 0);
    const float msc = mg ? CQ : 256.0f * CQ;

    for (int u = u0; u < u1; u++) {
        if (u + 2 < u1)      asm volatile("cp.async.wait_group 2;" ::: "memory");
        else if (u + 1 < u1) asm volatile("cp.async.wait_group 1;" ::: "memory");
        else                 asm volatile("cp.async.wait_group 0;" ::: "memory");
        __syncthreads();
        if (u + 3 < u1) issue_unit(sb, tid, u + 3, (u + 3 - u0) & (STAGES - 1), qw);

        uint32_t aBase = sb + (uint32_t)((u - u0) & (STAGES - 1)) * STAGE_BYTES;
        uint32_t qBase = aBase + 8192;
        // thread's Q base: kword tg2, col 2*nrow within its 32-col group
        uint32_t qn = qBase + (uint32_t)tg2 * 512 + (uint32_t)(ng * 32 + 2 * nrow) * 4;
        uint32_t aRow = aBase + (uint32_t)(mg * 32 + lrow) * 128;
        uint32_t swz = (uint32_t)(lrow & 7) << 4;

        #pragma unroll
        for (int kk = 0; kk < 4; kk++) {
            uint32_t a0[4], a1[4];
            uint32_t ad = aRow + (((uint32_t)(kk * 2 + lcb) << 4) ^ swz);
            ldmx4(a0, ad);
            ldmx4(a1, ad + 16 * 128);

            // w[sp][half] as v2: .x = col 2n (slice even), .y = col 2n+1 (odd)
            uint32_t w00x, w00y, w01x, w01y, w10x, w10y, w11x, w11y;
            uint32_t qk = qn + (uint32_t)(kk * 2048);
            LDS64(w00x, w00y, qk);                 // sp0, half0 (kw = kk*4+tg2)
            LDS64(w01x, w01y, qk + 1024);          // sp0, half1 (kw + 2)
            LDS64(w10x, w10y, qk + 64);            // sp1 (+16 cols), half0
            LDS64(w11x, w11y, qk + 64 + 1024);     // sp1, half1

            uint32_t b00 = (w00x >> sh) & 0x0F0F0F0Fu;   // j=0
            uint32_t b01 = (w01x >> sh) & 0x0F0F0F0Fu;
            uint32_t b10 = (w00y >> sh) & 0x0F0F0F0Fu;   // j=1
            uint32_t b11 = (w01y >> sh) & 0x0F0F0F0Fu;
            uint32_t b20 = (w10x >> sh) & 0x0F0F0F0Fu;   // j=2
            uint32_t b21 = (w11x >> sh) & 0x0F0F0F0Fu;
            uint32_t b30 = (w10y >> sh) & 0x0F0F0F0Fu;   // j=3
            uint32_t b31 = (w11y >> sh) & 0x0F0F0F0Fu;

            imma16832(acc[0][0], a0, b00, b01);
            imma16832(acc[1][0], a1, b00, b01);
            imma16832(acc[0][1], a0, b10, b11);
            imma16832(acc[1][1], a1, b10, b11);
            imma16832(acc[0][2], a0, b20, b21);
            imma16832(acc[1][2], a1, b20, b21);
            imma16832(acc[0][3], a0, b30, b31);
            imma16832(acc[1][3], a1, b30, b31);
        }

        // flush at segment end (tile boundary or range end)
        bool last = (u + 1 == u1);
        if (last || ((u + 1) >> 5) != seg_nt) {
            int n0 = seg_nt * TILE_N;
            #pragma unroll
            for (int mt = 0; mt < 2; mt++) {
                #pragma unroll
                for (int j = 0; j < 4; j++) {
                    // paired-column mapping: g(j,f) = (j&2)*8 + 2f + (j&1)
                    int c0 = n0 + ng * 32 + ((j & 2) << 3) + 4 * j4 + (j & 1);
                    int c1 = c0 + 2;
                    float s0 = __ldg(scales + c0) * msc;
                    float s1 = __ldg(scales + c1) * msc;
                    int r0 = mt * 16 + nrow;
                    int r1 = r0 + 8;
                    float v00 = s0 * (float)acc[mt][j][0];
                    float v01 = s1 * (float)acc[mt][j][1];
                    float v10 = s0 * (float)acc[mt][j][2];
                    float v11 = s1 * (float)acc[mt][j][3];
                    if (seg_first && mg == 0) {
                        float z0 = __ldg(zeros + c0), z1 = __ldg(zeros + c1);
                        float b0 = __ldg(bias + c0),  b1 = __ldg(bias + c1);
                        float S0 = S_sm[r0], S1 = S_sm[r1];
                        v00 += b0 - S0 * z0;
                        v01 += b1 - S0 * z1;
                        v10 += b0 - S1 * z0;
                        v11 += b1 - S1 * z1;
                    }
                    atomicAdd(out + (size_t)r0 * NTOT + c0, v00);
                    atomicAdd(out + (size_t)r0 * NTOT + c1, v01);
                    atomicAdd(out + (size_t)r1 * NTOT + c0, v10);
                    atomicAdd(out + (size_t)r1 * NTOT + c1, v11);
                    #pragma unroll
                    for (int i = 0; i < 4; i++) acc[mt][j][i] = 0;
                }
            }
            if (!last) {
                seg_nt = (u + 1) >> 5;
                seg_first = true;
            }
        }
    }
}

// ---------------------------------------------------------------------------
extern "C" void kernel_launch(void* const* d_in, const int* in_sizes, int n_in,
                              void* d_out, int out_size) {
    const float* x      = (const float*)d_in[0];
    const int*   qw     = (const int*)d_in[1];
    const float* scales = (const float*)d_in[2];
    const float* zeros  = (const float*)d_in[3];
    const float* bias   = (const float*)d_in[4];
    float* out = (float*)d_out;

    cudaFuncSetAttribute(gemm_kernel, cudaFuncAttributeMaxDynamicSharedMemorySize, SMEM_TOTAL);

    prep_kernel<<<128, 128>>>(x, out);
    gemm_kernel<<<GRID, THREADS, SMEM_TOTAL>>>(qw, scales, zeros, bias, out);
}

// round 14
// speedup vs baseline: 1.0451x; 1.0451x over previous
#include <cuda_runtime.h>
#include <cstdint>

// ============================================================================
// QuantLinear: y = x @ (scales*q - zeros) + bias        (sm_100 portable path)
//   x:[32,4096] f32, qweight:[512,11008] i32 (8 nibbles/word along K),
//   scales/zeros/bias:[11008] f32, out:[32,11008] f32
//
// INT8 tensor-core path, fixed scale c = 2^-12:  x ~= c*(256*h + l), h,l s8.
//   prep:  128 blocks: quantize+permute (0,2,4,6,1,3,5,7) within groups of 8,
//          rows 0-31 = h, rows 32-63 = l; partial row sums; zeroes out[].
//   gemm:  persistent-balanced 2752 units over 296 CTAs.
//          *** loads via cp.async.bulk + mbarrier (80 bulk ops/unit instead
//          of 1024 LDGSTS — the LDGSTS issue rate was the binder). ***
//          A stored at 144B row pitch -> conflict-free LDSM without swizzle.
//          mma.m16n8k32.s32.s8.s8 (R11 compute body, proven).
//          Epilogue: atomicAdd(out, s*c*(256*Dh+Dl) [+ b - S*z on chunk-0]).
// ============================================================================

#define KTOT   4096
#define NTOT   11008
#define MTOK   32
#define TILE_N 128
#define TILE_K 128
#define NTILES 86
#define UNITS  (NTILES * 32)      // 2752
#define GRID   296                // 2 x 148 SMs
#define THREADS 256
#define STAGES 4

#define CQ (1.0f / 4096.0f)       // fixed quant scale

#define A_PITCH 144
#define A_BYTES (64 * A_PITCH)    // 9216
#define Q_OFF   A_BYTES
#define STAGE_BYTES (A_BYTES + 8192)   // 17408
#define SM_BAR (STAGES * STAGE_BYTES)  // 69632: 4 mbarriers
#define SM_S   (SM_BAR + 64)
#define SMEM_TOTAL (SM_S + 128)

#define OUTN (MTOK * NTOT)

__device__ __align__(16) int8_t g_A[64 * KTOT];
__device__ float g_Spart[128];    // 4 partials per token

// ---------------------------------------------------------------------------
__device__ __forceinline__ uint32_t smem_u32(const void* p) {
    uint32_t a;
    asm("{ .reg .u64 t; cvta.to.shared.u64 t, %1; cvt.u32.u64 %0, t; }"
        : "=r"(a) : "l"(p));
    return a;
}

#define MBAR_INIT(addr, cnt) \
    asm volatile("mbarrier.init.shared.b64 [%0], %1;" :: "r"(addr), "r"(cnt) : "memory")
#define MBAR_EXPECT(addr, bytes) \
    asm volatile("mbarrier.arrive.expect_tx.shared.b64 _, [%0], %1;" \
                 :: "r"(addr), "r"(bytes) : "memory")
#define BULK_G2S(dst, src, bytes, bar) \
    asm volatile("cp.async.bulk.shared::cta.global.mbarrier::complete_tx::bytes " \
                 "[%0], [%1], %2, [%3];" \
                 :: "r"(dst), "l"(src), "r"(bytes), "r"(bar) : "memory")
#define MBAR_WAIT(addr, phase) do {                                              \
    uint32_t _m = (addr); uint32_t _p = (phase); uint32_t _d;                    \
    asm volatile("{\n\t.reg .pred p;\n\t"                                        \
        "mbarrier.try_wait.parity.shared.b64 p, [%1], %2;\n\t"                   \
        "selp.b32 %0, 1, 0, p;\n\t}" : "=r"(_d) : "r"(_m), "r"(_p) : "memory");  \
    if (!_d) {                                                                   \
        asm volatile("{\n\t.reg .pred P1;\n\t"                                   \
            "WL%=:\n\t"                                                          \
            "mbarrier.try_wait.parity.shared.b64 P1, [%0], %1;\n\t"              \
            "@P1 bra.uni WD%=;\n\t"                                              \
            "bra.uni WL%=;\n\t"                                                  \
            "WD%=:\n\t}" :: "r"(_m), "r"(_p) : "memory");                        \
    }                                                                            \
} while (0)

__device__ __forceinline__ void imma16832(int* d, const uint32_t* a,
                                          uint32_t b0, uint32_t b1) {
    asm volatile(
        "mma.sync.aligned.m16n8k32.row.col.s32.s8.s8.s32 "
        "{%0,%1,%2,%3}, {%4,%5,%6,%7}, {%8,%9}, {%0,%1,%2,%3};"
        : "+r"(d[0]), "+r"(d[1]), "+r"(d[2]), "+r"(d[3])
        : "r"(a[0]), "r"(a[1]), "r"(a[2]), "r"(a[3]), "r"(b0), "r"(b1));
}

__device__ __forceinline__ void ldmx4(uint32_t* a, uint32_t addr) {
    asm volatile("ldmatrix.sync.aligned.m8n8.x4.shared.b16 {%0,%1,%2,%3}, [%4];"
                 : "=r"(a[0]), "=r"(a[1]), "=r"(a[2]), "=r"(a[3]) : "r"(addr));
}

__device__ __forceinline__ uint32_t lds32(uint32_t addr) {
    uint32_t v;
    asm volatile("ld.shared.b32 %0, [%1];" : "=r"(v) : "r"(addr));
    return v;
}

// ---------------------------------------------------------------------------
// prep: 128 blocks (32 tokens x 4 slices) x 128 threads; thread = one group
// of 8 k-values. Fixed c = 2^-12.
// ---------------------------------------------------------------------------
__global__ void __launch_bounds__(128, 4) prep_kernel(const float* __restrict__ x,
                                                      float* __restrict__ out) {
    int t = blockIdx.x >> 2, sl = blockIdx.x & 3, tid = threadIdx.x;
    int k0 = sl * 1024 + tid * 8;
    const float4* p = (const float4*)(x + (size_t)t * KTOT + k0);
    float4 va = p[0], vb = p[1];
    float v[8] = {va.x, va.y, va.z, va.w, vb.x, vb.y, vb.z, vb.w};

    int hq[8], lq[8];
    int hsum = 0, lsum = 0;
    #pragma unroll
    for (int i = 0; i < 8; i++) {
        float hf = rintf(v[i] * 16.0f);            // x / (256*c), 256c = 1/16
        int h = (int)hf;
        float r = fmaf(hf, -0.0625f, v[i]);        // x - 256c*h
        int l = (int)rintf(r * 4096.0f);           // r / c
        if (l == 128) { l = -128; h += 1; }
        hsum += h; lsum += l;
        int pp = (i >> 1) + ((i & 1) << 2);        // (0,2,4,6,1,3,5,7)
        hq[pp] = h; lq[pp] = l;
    }
    uint2 hw, lw;
    hw.x = (hq[0] & 0xFF) | ((hq[1] & 0xFF) << 8) | ((hq[2] & 0xFF) << 16) | ((hq[3] & 0xFF) << 24);
    hw.y = (hq[4] & 0xFF) | ((hq[5] & 0xFF) << 8) | ((hq[6] & 0xFF) << 16) | ((hq[7] & 0xFF) << 24);
    lw.x = (lq[0] & 0xFF) | ((lq[1] & 0xFF) << 8) | ((lq[2] & 0xFF) << 16) | ((lq[3] & 0xFF) << 24);
    lw.y = (lq[4] & 0xFF) | ((lq[5] & 0xFF) << 8) | ((lq[6] & 0xFF) << 16) | ((lq[7] & 0xFF) << 24);
    *(uint2*)(g_A + (size_t)t * KTOT + k0) = hw;
    *(uint2*)(g_A + (size_t)(t + 32) * KTOT + k0) = lw;

    // zero out[]
    int gtid = blockIdx.x * 128 + tid;
    const float4 z4 = {0.f, 0.f, 0.f, 0.f};
    for (int i = gtid; i < OUTN / 4; i += 128 * 128)
        ((float4*)out)[i] = z4;

    // partial row sum: S_part = c*(256*H + L)
    float acc = 256.0f * (float)hsum + (float)lsum;
    #pragma unroll
    for (int off = 16; off; off >>= 1) acc += __shfl_down_sync(0xFFFFFFFFu, acc, off);
    __shared__ float red[4];
    if ((tid & 31) == 0) red[tid >> 5] = acc;
    __syncthreads();
    if (tid == 0)
        g_Spart[blockIdx.x] = CQ * (red[0] + red[1] + red[2] + red[3]);
}

// ---------------------------------------------------------------------------
// gemm (persistent balanced, INT8, cp.async.bulk loads)
// ---------------------------------------------------------------------------
__device__ __forceinline__ void issue_unit(uint32_t sb, int tid, int u, int slot,
                                           const int* __restrict__ qw) {
    int nt = u >> 5, cg = u & 31;
    uint32_t stage = sb + (uint32_t)slot * STAGE_BYTES;
    uint32_t bar = sb + SM_BAR + (uint32_t)slot * 8;
    if (tid < 64) {
        // A row tid: 128 bytes, dst pitch 144
        MBAR_EXPECT(bar, 128u);
        uint32_t dst = stage + (uint32_t)tid * A_PITCH;
        const char* src = (const char*)g_A + (size_t)tid * KTOT + (size_t)cg * TILE_K;
        BULK_G2S(dst, src, 128u, bar);
    } else if (tid < 80) {
        // Q kword row (tid-64): 512 bytes
        MBAR_EXPECT(bar, 512u);
        int kw = tid - 64;
        uint32_t dst = stage + Q_OFF + (uint32_t)kw * 512;
        const char* src = (const char*)qw +
            ((size_t)(cg * 16 + kw) * NTOT + (size_t)nt * TILE_N) * 4;
        BULK_G2S(dst, src, 512u, bar);
    }
}

__global__ void __launch_bounds__(THREADS, 2) gemm_kernel(
    const int* __restrict__ qw, const float* __restrict__ scales,
    const float* __restrict__ zeros, const float* __restrict__ bias,
    float* __restrict__ out) {
    extern __shared__ __align__(1024) char smem[];
    uint32_t sb = smem_u32(smem);
    int tid = threadIdx.x, wid = tid >> 5, lane = tid & 31;
    float* S_sm = (float*)(smem + SM_S);

    int u0 = (int)(((long long)blockIdx.x * UNITS) / GRID);
    int u1 = (int)(((long long)(blockIdx.x + 1) * UNITS) / GRID);

    if (tid < 4) MBAR_INIT(sb + SM_BAR + tid * 8, 80u);
    if (tid < 32)
        S_sm[tid] = g_Spart[tid * 4] + g_Spart[tid * 4 + 1] +
                    g_Spart[tid * 4 + 2] + g_Spart[tid * 4 + 3];
    __syncthreads();
    asm volatile("fence.proxy.async.shared::cta;" ::: "memory");

    if (u0 + 0 < u1) issue_unit(sb, tid, u0 + 0, 0, qw);
    if (u0 + 1 < u1) issue_unit(sb, tid, u0 + 1, 1, qw);
    if (u0 + 2 < u1) issue_unit(sb, tid, u0 + 2, 2, qw);

    const int lrow = lane & 15;
    const int lcb  = lane >> 4;
    const int j4   = lane & 3;
    const int nrow = lane >> 2;
    const uint32_t sh = (uint32_t)((j4 & 1) * 4);
    const int tg2 = j4 >> 1;

    int accH[2][2][4], accL[2][2][4];
    #pragma unroll
    for (int mt = 0; mt < 2; mt++)
        #pragma unroll
        for (int j = 0; j < 2; j++)
            #pragma unroll
            for (int i = 0; i < 4; i++) { accH[mt][j][i] = 0; accL[mt][j][i] = 0; }

    int seg_nt = u0 >> 5;
    bool seg_first = ((u0 & 31) == 0);
    uint32_t ph = 0;                     // per-slot phase parity bits

    for (int u = u0; u < u1; u++) {
        int slot = (u - u0) & 3;
        MBAR_WAIT(sb + SM_BAR + slot * 8, (ph >> slot) & 1u);
        ph ^= 1u << slot;
        __syncthreads();                 // all warps done with slot (u-1)%4
        if (u + 3 < u1) issue_unit(sb, tid, u + 3, (u + 3 - u0) & 3, qw);

        uint32_t aBase = sb + (uint32_t)slot * STAGE_BYTES;
        uint32_t qBase = aBase + Q_OFF;
        uint32_t q0 = qBase + (uint32_t)tg2 * 512 + (uint32_t)(wid * 16 + nrow) * 4;
        uint32_t q1 = q0 + 8 * 4;
        uint32_t aRow = aBase + (uint32_t)lrow * A_PITCH;

        // w double-buffer: [buf][slice*2 + half]
        uint32_t w[2][4];
        w[0][0] = lds32(q0);
        w[0][1] = lds32(q0 + 1024);
        w[0][2] = lds32(q1);
        w[0][3] = lds32(q1 + 1024);

        #pragma unroll
        for (int kk = 0; kk < 4; kk++) {
            int cur = kk & 1, nx = cur ^ 1;
            uint32_t a[4][4];
            uint32_t ad = aRow + ((uint32_t)(kk * 2 + lcb) << 4);
            ldmx4(a[0], ad);
            ldmx4(a[1], ad + 16 * A_PITCH);
            ldmx4(a[2], ad + 32 * A_PITCH);
            ldmx4(a[3], ad + 48 * A_PITCH);
            if (kk < 3) {
                w[nx][0] = lds32(q0 + (kk + 1) * 2048);
                w[nx][1] = lds32(q0 + (kk + 1) * 2048 + 1024);
                w[nx][2] = lds32(q1 + (kk + 1) * 2048);
                w[nx][3] = lds32(q1 + (kk + 1) * 2048 + 1024);
            }
            uint32_t b00 = (w[cur][0] >> sh) & 0x0F0F0F0Fu;
            uint32_t b01 = (w[cur][1] >> sh) & 0x0F0F0F0Fu;
            uint32_t b10 = (w[cur][2] >> sh) & 0x0F0F0F0Fu;
            uint32_t b11 = (w[cur][3] >> sh) & 0x0F0F0F0Fu;

            imma16832(accH[0][0], a[0], b00, b01);
            imma16832(accH[1][0], a[1], b00, b01);
            imma16832(accL[0][0], a[2], b00, b01);
            imma16832(accL[1][0], a[3], b00, b01);
            imma16832(accH[0][1], a[0], b10, b11);
            imma16832(accH[1][1], a[1], b10, b11);
            imma16832(accL[0][1], a[2], b10, b11);
            imma16832(accL[1][1], a[3], b10, b11);
        }

        // flush at segment end (tile boundary or range end)
        bool last = (u + 1 == u1);
        if (last || ((u + 1) >> 5) != seg_nt) {
            int n0 = seg_nt * TILE_N;
            #pragma unroll
            for (int mt = 0; mt < 2; mt++) {
                #pragma unroll
                for (int j = 0; j < 2; j++) {
                    int ncl = wid * 16 + j * 8 + j4 * 2;
                    int col = n0 + ncl;
                    float s0 = __ldg(scales + col) * CQ;
                    float s1 = __ldg(scales + col + 1) * CQ;
                    int r0 = mt * 16 + nrow;
                    int r1 = r0 + 8;
                    float f00 = 256.0f * (float)accH[mt][j][0] + (float)accL[mt][j][0];
                    float f01 = 256.0f * (float)accH[mt][j][1] + (float)accL[mt][j][1];
                    float f10 = 256.0f * (float)accH[mt][j][2] + (float)accL[mt][j][2];
                    float f11 = 256.0f * (float)accH[mt][j][3] + (float)accL[mt][j][3];
                    float v00 = s0 * f00, v01 = s1 * f01;
                    float v10 = s0 * f10, v11 = s1 * f11;
                    if (seg_first) {
                        float z0 = __ldg(zeros + col), z1 = __ldg(zeros + col + 1);
                        float b0 = __ldg(bias + col),  b1 = __ldg(bias + col + 1);
                        float S0 = S_sm[r0], S1 = S_sm[r1];
                        v00 += b0 - S0 * z0;
                        v01 += b1 - S0 * z1;
                        v10 += b0 - S1 * z0;
                        v11 += b1 - S1 * z1;
                    }
                    atomicAdd(out + (size_t)r0 * NTOT + col,     v00);
                    atomicAdd(out + (size_t)r0 * NTOT + col + 1, v01);
                    atomicAdd(out + (size_t)r1 * NTOT + col,     v10);
                    atomicAdd(out + (size_t)r1 * NTOT + col + 1, v11);
                    #pragma unroll
                    for (int i = 0; i < 4; i++) { accH[mt][j][i] = 0; accL[mt][j][i] = 0; }
                }
            }
            if (!last) {
                seg_nt = (u + 1) >> 5;
                seg_first = true;
            }
        }
    }
}

// ---------------------------------------------------------------------------
extern "C" void kernel_launch(void* const* d_in, const int* in_sizes, int n_in,
                              void* d_out, int out_size) {
    const float* x      = (const float*)d_in[0];
    const int*   qw     = (const int*)d_in[1];
    const float* scales = (const float*)d_in[2];
    const float* zeros  = (const float*)d_in[3];
    const float* bias   = (const float*)d_in[4];
    float* out = (float*)d_out;

    cudaFuncSetAttribute(gemm_kernel, cudaFuncAttributeMaxDynamicSharedMemorySize, SMEM_TOTAL);

    prep_kernel<<<128, 128>>>(x, out);
    gemm_kernel<<<GRID, THREADS, SMEM_TOTAL>>>(qw, scales, zeros, bias, out);
}

// round 15
// speedup vs baseline: 1.2579x; 1.2036x over previous
#include <cuda_runtime.h>
#include <cuda_fp16.h>
#include <cstdint>

// ============================================================================
// QuantLinear: y = x @ (scales*q - zeros) + bias        (sm_100 portable path)
//   x:[32,4096] f32, qweight:[512,11008] i32 (8 nibbles/word along K),
//   scales/zeros/bias:[11008] f32, out:[32,11008] f32
//
//   prep:  g_A[32,4096] = fp16(x) permuted (0,4,1,5,2,6,3,7) within groups of
//          8; partial row sums -> g_Spart[128]; ALSO zeroes out[].
//   gemm:  persistent-balanced: 2752 (ntile,chunk) units over 444 CTAs
//          (*** 3 per SM — occupancy push; kk loop single-buffered to fit
//          85 regs ***). 4-stage cp.async pipeline. mma.m16n8k16 fp16->f32;
//          B dequant ((w>>4*j4)&0x000F000F)|0x64006400. Flush per tile
//          segment: atomicAdd(out, s*D [+ b - S*(1024*s+z) on chunk-0 seg]).
// ============================================================================

#define KTOT   4096
#define NTOT   11008
#define MTOK   32
#define TILE_N 128
#define TILE_K 128
#define NCHUNK 32                 // K chunks per ntile
#define NTILES 86
#define UNITS  (NTILES * NCHUNK)  // 2752
#define GRID   444                // 3 x 148 SMs
#define THREADS 256
#define STAGES 4

#define STAGE_BYTES 16384         // A 8192 + Q 8192
#define SM_S (STAGES * STAGE_BYTES)
#define SMEM_TOTAL (SM_S + 128)   // + S[32]

#define OUTN (MTOK * NTOT)        // 352256

__device__ __half g_A[MTOK * KTOT];
__device__ float  g_Spart[128];   // 4 partials per token

// ---------------------------------------------------------------------------
__device__ __forceinline__ uint32_t smem_u32(const void* p) {
    uint32_t a;
    asm("{ .reg .u64 t; cvta.to.shared.u64 t, %1; cvt.u32.u64 %0, t; }"
        : "=r"(a) : "l"(p));
    return a;
}

#define CP16(dst, src) \
    asm volatile("cp.async.cg.shared.global [%0], [%1], 16;" :: "r"(dst), "l"(src))
#define CP_COMMIT() asm volatile("cp.async.commit_group;" ::: "memory")

__device__ __forceinline__ void mma16816(float* d, const uint32_t* a,
                                         uint32_t b0, uint32_t b1) {
    asm volatile(
        "mma.sync.aligned.m16n8k16.row.col.f32.f16.f16.f32 "
        "{%0,%1,%2,%3}, {%4,%5,%6,%7}, {%8,%9}, {%0,%1,%2,%3};"
        : "+f"(d[0]), "+f"(d[1]), "+f"(d[2]), "+f"(d[3])
        : "r"(a[0]), "r"(a[1]), "r"(a[2]), "r"(a[3]), "r"(b0), "r"(b1));
}

__device__ __forceinline__ void ldmx4(uint32_t* a, uint32_t addr) {
    asm volatile("ldmatrix.sync.aligned.m8n8.x4.shared.b16 {%0,%1,%2,%3}, [%4];"
                 : "=r"(a[0]), "=r"(a[1]), "=r"(a[2]), "=r"(a[3]) : "r"(addr));
}

__device__ __forceinline__ uint32_t lds32(uint32_t addr) {
    uint32_t v;
    asm volatile("ld.shared.b32 %0, [%1];" : "=r"(v) : "r"(addr));
    return v;
}

// ---------------------------------------------------------------------------
// prep: fp16-convert + permute x, partial row sums, and zero out[].
// ---------------------------------------------------------------------------
__global__ void __launch_bounds__(128, 4) prep_kernel(const float* __restrict__ x,
                                                      float* __restrict__ out) {
    int t = blockIdx.x >> 2, sl = blockIdx.x & 3, tid = threadIdx.x;
    int k0 = sl * 1024 + tid * 8;
    const float4* src = (const float4*)(x + (size_t)t * KTOT + k0);
    float4 v0 = src[0];
    float4 v1 = src[1];
    __half h0 = __float2half(v0.x), h1 = __float2half(v0.y);
    __half h2 = __float2half(v0.z), h3 = __float2half(v0.w);
    __half h4 = __float2half(v1.x), h5 = __float2half(v1.y);
    __half h6 = __float2half(v1.z), h7 = __float2half(v1.w);
    float acc = __half2float(h0) + __half2float(h1) + __half2float(h2) +
                __half2float(h3) + __half2float(h4) + __half2float(h5) +
                __half2float(h6) + __half2float(h7);
    uint4 o;
    o.x = (uint32_t)__half_as_ushort(h0) | ((uint32_t)__half_as_ushort(h4) << 16);
    o.y = (uint32_t)__half_as_ushort(h1) | ((uint32_t)__half_as_ushort(h5) << 16);
    o.z = (uint32_t)__half_as_ushort(h2) | ((uint32_t)__half_as_ushort(h6) << 16);
    o.w = (uint32_t)__half_as_ushort(h3) | ((uint32_t)__half_as_ushort(h7) << 16);
    *(uint4*)(g_A + (size_t)t * KTOT + k0) = o;

    // zero out[] (float4 strided over all prep threads)
    int gtid = blockIdx.x * 128 + tid;
    const float4 z4 = {0.f, 0.f, 0.f, 0.f};
    for (int i = gtid; i < OUTN / 4; i += 128 * 128)
        ((float4*)out)[i] = z4;

    __shared__ float red[4];
    #pragma unroll
    for (int off = 16; off; off >>= 1) acc += __shfl_down_sync(0xFFFFFFFFu, acc, off);
    if ((tid & 31) == 0) red[tid >> 5] = acc;
    __syncthreads();
    if (tid == 0)
        g_Spart[blockIdx.x] = red[0] + red[1] + red[2] + red[3];
}

// ---------------------------------------------------------------------------
// gemm (persistent balanced, 3 CTAs/SM)
// ---------------------------------------------------------------------------
__device__ __forceinline__ void issue_unit(uint32_t sb, int tid, int u, int slot,
                                           const int* __restrict__ qw) {
    int nt = u >> 5, cg = u & 31;
    int n0 = nt * TILE_N;
    uint32_t stage = sb + (uint32_t)slot * STAGE_BYTES;
    // A: 32 rows x 16 chunks of 16B (swizzled) — depends only on cg
    #pragma unroll
    for (int i = 0; i < 2; i++) {
        int seg = tid + i * 256;
        int r = seg >> 4, cc = seg & 15;
        uint32_t dst = stage + r * 256 + (((uint32_t)cc ^ (uint32_t)(r & 7)) << 4);
        const char* src = (const char*)g_A + ((size_t)r * KTOT + (size_t)cg * TILE_K) * 2 + cc * 16;
        CP16(dst, src);
    }
    // Q: 16 kwords x 32 segs of 16B
    #pragma unroll
    for (int i = 0; i < 2; i++) {
        int seg = tid + i * 256;
        int kw = seg >> 5, ns = seg & 31;
        uint32_t dst = stage + 8192 + kw * 512 + ns * 16;
        const char* src = (const char*)qw + ((size_t)(cg * 16 + kw) * NTOT + n0) * 4 + ns * 16;
        CP16(dst, src);
    }
    CP_COMMIT();
}

__global__ void __launch_bounds__(THREADS, 3) gemm_kernel(
    const int* __restrict__ qw, const float* __restrict__ scales,
    const float* __restrict__ zeros, const float* __restrict__ bias,
    float* __restrict__ out) {
    extern __shared__ __align__(1024) char smem[];
    uint32_t sb = smem_u32(smem);
    int tid = threadIdx.x, wid = tid >> 5, lane = tid & 31;
    float* S_sm = (float*)(smem + SM_S);

    int u0 = (int)(((long long)blockIdx.x * UNITS) / GRID);
    int u1 = (int)(((long long)(blockIdx.x + 1) * UNITS) / GRID);

    if (tid < 32)
        S_sm[tid] = g_Spart[tid * 4] + g_Spart[tid * 4 + 1] +
                    g_Spart[tid * 4 + 2] + g_Spart[tid * 4 + 3];

    // prologue: up to 3 units in flight
    if (u0 + 0 < u1) issue_unit(sb, tid, u0 + 0, 0, qw);
    if (u0 + 1 < u1) issue_unit(sb, tid, u0 + 1, 1, qw);
    if (u0 + 2 < u1) issue_unit(sb, tid, u0 + 2, 2, qw);

    const int lrow = lane & 15;
    const int lcb  = lane >> 4;
    const int j4   = lane & 3;
    const int nrow = lane >> 2;
    const uint32_t sh4 = (uint32_t)(j4 * 4);

    float acc[2][2][4];
    #pragma unroll
    for (int mt = 0; mt < 2; mt++)
        #pragma unroll
        for (int j = 0; j < 2; j++)
            #pragma unroll
            for (int i = 0; i < 4; i++) acc[mt][j][i] = 0.f;

    int seg_nt = u0 >> 5;
    bool seg_first = ((u0 & 31) == 0);

    for (int u = u0; u < u1; u++) {
        // wait so the current unit's group has landed
        if (u + 2 < u1)      asm volatile("cp.async.wait_group 2;" ::: "memory");
        else if (u + 1 < u1) asm volatile("cp.async.wait_group 1;" ::: "memory");
        else                 asm volatile("cp.async.wait_group 0;" ::: "memory");
        __syncthreads();
        if (u + 3 < u1) issue_unit(sb, tid, u + 3, (u + 3 - u0) & (STAGES - 1), qw);

        uint32_t aBase = sb + (uint32_t)((u - u0) & (STAGES - 1)) * STAGE_BYTES;
        uint32_t qBase = aBase + 8192;
        uint32_t q0 = qBase + (uint32_t)(wid * 16 + nrow) * 4;   // j=0 n-slice
        uint32_t q1 = q0 + 8 * 4;                                 // j=1 n-slice
        uint32_t aRow = aBase + (uint32_t)lrow * 256;

        // single-buffered kk loop (regs freed for 3-CTA occupancy; the
        // exposed LDS/LDSM latency is hidden by 6 warps/SMSP)
        #pragma unroll
        for (int kk = 0; kk < 8; kk++) {
            uint32_t a0[4], a1[4];
            uint32_t cc = (uint32_t)(kk * 2 + lcb);
            uint32_t ad = aRow + ((cc ^ (uint32_t)(lrow & 7)) << 4);
            ldmx4(a0, ad);
            ldmx4(a1, ad + 16 * 256);

            uint32_t w0 = lds32(q0 + kk * 1024);
            uint32_t w1 = lds32(q0 + kk * 1024 + 512);
            uint32_t w2 = lds32(q1 + kk * 1024);
            uint32_t w3 = lds32(q1 + kk * 1024 + 512);

            uint32_t b00 = ((w0 >> sh4) & 0x000F000Fu) | 0x64006400u;
            uint32_t b01 = ((w1 >> sh4) & 0x000F000Fu) | 0x64006400u;
            uint32_t b10 = ((w2 >> sh4) & 0x000F000Fu) | 0x64006400u;
            uint32_t b11 = ((w3 >> sh4) & 0x000F000Fu) | 0x64006400u;

            mma16816(acc[0][0], a0, b00, b01);
            mma16816(acc[1][0], a1, b00, b01);
            mma16816(acc[0][1], a0, b10, b11);
            mma16816(acc[1][1], a1, b10, b11);
        }

        // flush at segment end (tile boundary or range end)
        bool last = (u + 1 == u1);
        if (last || ((u + 1) >> 5) != seg_nt) {
            int n0 = seg_nt * TILE_N;
            #pragma unroll
            for (int mt = 0; mt < 2; mt++) {
                #pragma unroll
                for (int j = 0; j < 2; j++) {
                    int ncl = wid * 16 + j * 8 + j4 * 2;
                    int col = n0 + ncl;
                    float s0 = __ldg(scales + col), s1 = __ldg(scales + col + 1);
                    int r0 = mt * 16 + nrow;
                    int r1 = r0 + 8;
                    float v00 = s0 * acc[mt][j][0];
                    float v01 = s1 * acc[mt][j][1];
                    float v10 = s0 * acc[mt][j][2];
                    float v11 = s1 * acc[mt][j][3];
                    if (seg_first) {
                        float c0 = fmaf(1024.f, s0, __ldg(zeros + col));
                        float c1 = fmaf(1024.f, s1, __ldg(zeros + col + 1));
                        float b0 = __ldg(bias + col);
                        float b1 = __ldg(bias + col + 1);
                        float S0 = S_sm[r0], S1 = S_sm[r1];
                        v00 += b0 - S0 * c0;
                        v01 += b1 - S0 * c1;
                        v10 += b0 - S1 * c0;
                        v11 += b1 - S1 * c1;
                    }
                    atomicAdd(out + (size_t)r0 * NTOT + col,     v00);
                    atomicAdd(out + (size_t)r0 * NTOT + col + 1, v01);
                    atomicAdd(out + (size_t)r1 * NTOT + col,     v10);
                    atomicAdd(out + (size_t)r1 * NTOT + col + 1, v11);
                    acc[mt][j][0] = acc[mt][j][1] = acc[mt][j][2] = acc[mt][j][3] = 0.f;
                }
            }
            if (!last) {
                seg_nt = (u + 1) >> 5;
                seg_first = true;        // boundary segments start at chunk 0
            }
        }
    }
}

// ---------------------------------------------------------------------------
extern "C" void kernel_launch(void* const* d_in, const int* in_sizes, int n_in,
                              void* d_out, int out_size) {
    const float* x      = (const float*)d_in[0];
    const int*   qw     = (const int*)d_in[1];
    const float* scales = (const float*)d_in[2];
    const float* zeros  = (const float*)d_in[3];
    const float* bias   = (const float*)d_in[4];
    float* out = (float*)d_out;

    cudaFuncSetAttribute(gemm_kernel, cudaFuncAttributeMaxDynamicSharedMemorySize, SMEM_TOTAL);

    prep_kernel<<<128, 128>>>(x, out);
    gemm_kernel<<<GRID, THREADS, SMEM_TOTAL>>>(qw, scales, zeros, bias, out);
}

// round 16
// speedup vs baseline: 1.2890x; 1.0247x over previous
#include <cuda_runtime.h>
#include <cuda_fp16.h>
#include <cstdint>

// ============================================================================
// QuantLinear: y = x @ (scales*q - zeros) + bias        (sm_100 portable path)
//   x:[32,4096] f32, qweight:[512,11008] i32 (8 nibbles/word along K),
//   scales/zeros/bias:[11008] f32, out:[32,11008] f32
//
//   prep:  g_A[32,4096] = fp16(x) permuted (0,4,1,5,2,6,3,7) within groups of
//          8; partial row sums -> g_Spart[128]; ALSO zeroes out[].
//   gemm:  persistent-balanced: 86 N-tiles x 16 K-chunks of 256 = 1376 units
//          over 296 CTAs (2/SM). *** TILE_K=256: per-unit barrier/pipeline
//          overhead halved vs R9; zero extra accumulator registers. ***
//          3-stage cp.async pipeline (depth 2). mma.m16n8k16 fp16->f32;
//          register-double-buffered 16-deep kk loop; B dequant
//          ((w>>4*j4)&0x000F000F)|0x64006400. Flush per tile segment:
//          atomicAdd(out, s*D [+ b - S*(1024*s+z) on chunk-0 segment]).
// ============================================================================

#define KTOT   4096
#define NTOT   11008
#define MTOK   32
#define TILE_N 128
#define TILE_K 256
#define NCHUNK 16                 // K chunks per ntile
#define NTILES 86
#define UNITS  (NTILES * NCHUNK)  // 1376
#define GRID   296                // 2 x 148 SMs
#define THREADS 256
#define STAGES 3

#define STAGE_BYTES 32768         // A 16384 (32 rows x 512B) + Q 16384
#define SM_S (STAGES * STAGE_BYTES)
#define SMEM_TOTAL (SM_S + 128)   // + S[32]

#define OUTN (MTOK * NTOT)        // 352256

__device__ __half g_A[MTOK * KTOT];
__device__ float  g_Spart[128];   // 4 partials per token

// ---------------------------------------------------------------------------
__device__ __forceinline__ uint32_t smem_u32(const void* p) {
    uint32_t a;
    asm("{ .reg .u64 t; cvta.to.shared.u64 t, %1; cvt.u32.u64 %0, t; }"
        : "=r"(a) : "l"(p));
    return a;
}

#define CP16(dst, src) \
    asm volatile("cp.async.cg.shared.global [%0], [%1], 16;" :: "r"(dst), "l"(src))
#define CP_COMMIT() asm volatile("cp.async.commit_group;" ::: "memory")

__device__ __forceinline__ void mma16816(float* d, const uint32_t* a,
                                         uint32_t b0, uint32_t b1) {
    asm volatile(
        "mma.sync.aligned.m16n8k16.row.col.f32.f16.f16.f32 "
        "{%0,%1,%2,%3}, {%4,%5,%6,%7}, {%8,%9}, {%0,%1,%2,%3};"
        : "+f"(d[0]), "+f"(d[1]), "+f"(d[2]), "+f"(d[3])
        : "r"(a[0]), "r"(a[1]), "r"(a[2]), "r"(a[3]), "r"(b0), "r"(b1));
}

__device__ __forceinline__ void ldmx4(uint32_t* a, uint32_t addr) {
    asm volatile("ldmatrix.sync.aligned.m8n8.x4.shared.b16 {%0,%1,%2,%3}, [%4];"
                 : "=r"(a[0]), "=r"(a[1]), "=r"(a[2]), "=r"(a[3]) : "r"(addr));
}

__device__ __forceinline__ uint32_t lds32(uint32_t addr) {
    uint32_t v;
    asm volatile("ld.shared.b32 %0, [%1];" : "=r"(v) : "r"(addr));
    return v;
}

// ---------------------------------------------------------------------------
// prep: fp16-convert + permute x, partial row sums, and zero out[].
// ---------------------------------------------------------------------------
__global__ void __launch_bounds__(128, 4) prep_kernel(const float* __restrict__ x,
                                                      float* __restrict__ out) {
    int t = blockIdx.x >> 2, sl = blockIdx.x & 3, tid = threadIdx.x;
    int k0 = sl * 1024 + tid * 8;
    const float4* src = (const float4*)(x + (size_t)t * KTOT + k0);
    float4 v0 = src[0];
    float4 v1 = src[1];
    __half h0 = __float2half(v0.x), h1 = __float2half(v0.y);
    __half h2 = __float2half(v0.z), h3 = __float2half(v0.w);
    __half h4 = __float2half(v1.x), h5 = __float2half(v1.y);
    __half h6 = __float2half(v1.z), h7 = __float2half(v1.w);
    float acc = __half2float(h0) + __half2float(h1) + __half2float(h2) +
                __half2float(h3) + __half2float(h4) + __half2float(h5) +
                __half2float(h6) + __half2float(h7);
    uint4 o;
    o.x = (uint32_t)__half_as_ushort(h0) | ((uint32_t)__half_as_ushort(h4) << 16);
    o.y = (uint32_t)__half_as_ushort(h1) | ((uint32_t)__half_as_ushort(h5) << 16);
    o.z = (uint32_t)__half_as_ushort(h2) | ((uint32_t)__half_as_ushort(h6) << 16);
    o.w = (uint32_t)__half_as_ushort(h3) | ((uint32_t)__half_as_ushort(h7) << 16);
    *(uint4*)(g_A + (size_t)t * KTOT + k0) = o;

    // zero out[] (float4 strided over all prep threads)
    int gtid = blockIdx.x * 128 + tid;
    const float4 z4 = {0.f, 0.f, 0.f, 0.f};
    for (int i = gtid; i < OUTN / 4; i += 128 * 128)
        ((float4*)out)[i] = z4;

    __shared__ float red[4];
    #pragma unroll
    for (int off = 16; off; off >>= 1) acc += __shfl_down_sync(0xFFFFFFFFu, acc, off);
    if ((tid & 31) == 0) red[tid >> 5] = acc;
    __syncthreads();
    if (tid == 0)
        g_Spart[blockIdx.x] = red[0] + red[1] + red[2] + red[3];
}

// ---------------------------------------------------------------------------
// gemm (persistent balanced, TILE_K = 256)
// ---------------------------------------------------------------------------
__device__ __forceinline__ void issue_unit(uint32_t sb, int tid, int u, int slot,
                                           const int* __restrict__ qw) {
    int nt = u >> 4, cg = u & 15;
    int n0 = nt * TILE_N;
    uint32_t stage = sb + (uint32_t)slot * STAGE_BYTES;
    // A: 32 rows x 32 chunks of 16B (swizzled), 1024 segs
    #pragma unroll
    for (int i = 0; i < 4; i++) {
        int seg = tid + i * 256;
        int r = seg >> 5, cc = seg & 31;
        uint32_t dst = stage + r * 512 + (((uint32_t)(cc & 7) ^ (uint32_t)(r & 7)) << 4)
                     + (uint32_t)(cc & 24) * 16;
        const char* src = (const char*)g_A + ((size_t)r * KTOT + (size_t)cg * TILE_K) * 2 + cc * 16;
        CP16(dst, src);
    }
    // Q: 32 kwords x 32 segs of 16B, 1024 segs
    #pragma unroll
    for (int i = 0; i < 4; i++) {
        int seg = tid + i * 256;
        int kw = seg >> 5, ns = seg & 31;
        uint32_t dst = stage + 16384 + kw * 512 + ns * 16;
        const char* src = (const char*)qw + ((size_t)(cg * 32 + kw) * NTOT + n0) * 4 + ns * 16;
        CP16(dst, src);
    }
    CP_COMMIT();
}

__global__ void __launch_bounds__(THREADS, 2) gemm_kernel(
    const int* __restrict__ qw, const float* __restrict__ scales,
    const float* __restrict__ zeros, const float* __restrict__ bias,
    float* __restrict__ out) {
    extern __shared__ __align__(1024) char smem[];
    uint32_t sb = smem_u32(smem);
    int tid = threadIdx.x, wid = tid >> 5, lane = tid & 31;
    float* S_sm = (float*)(smem + SM_S);

    int u0 = (int)(((long long)blockIdx.x * UNITS) / GRID);
    int u1 = (int)(((long long)(blockIdx.x + 1) * UNITS) / GRID);

    if (tid < 32)
        S_sm[tid] = g_Spart[tid * 4] + g_Spart[tid * 4 + 1] +
                    g_Spart[tid * 4 + 2] + g_Spart[tid * 4 + 3];

    // prologue: 2 units in flight
    if (u0 + 0 < u1) issue_unit(sb, tid, u0 + 0, 0, qw);
    if (u0 + 1 < u1) issue_unit(sb, tid, u0 + 1, 1, qw);

    const int lrow = lane & 15;
    const int lcb  = lane >> 4;
    const int j4   = lane & 3;
    const int nrow = lane >> 2;
    const uint32_t sh4 = (uint32_t)(j4 * 4);

    float acc[2][2][4];
    #pragma unroll
    for (int mt = 0; mt < 2; mt++)
        #pragma unroll
        for (int j = 0; j < 2; j++)
            #pragma unroll
            for (int i = 0; i < 4; i++) acc[mt][j][i] = 0.f;

    int seg_nt = u0 >> 4;
    bool seg_first = ((u0 & 15) == 0);
    int slot = 0;

    for (int u = u0; u < u1; u++) {
        if (u + 1 < u1) asm volatile("cp.async.wait_group 1;" ::: "memory");
        else            asm volatile("cp.async.wait_group 0;" ::: "memory");
        __syncthreads();
        if (u + 2 < u1) {
            int s2 = slot + 2; if (s2 >= STAGES) s2 -= STAGES;
            issue_unit(sb, tid, u + 2, s2, qw);
        }

        uint32_t aBase = sb + (uint32_t)slot * STAGE_BYTES;
        uint32_t qBase = aBase + 16384;
        uint32_t q0 = qBase + (uint32_t)(wid * 16 + nrow) * 4;   // j=0 n-slice
        uint32_t q1 = q0 + 8 * 4;                                 // j=1 n-slice
        uint32_t aRow = aBase + (uint32_t)lrow * 512;
        uint32_t swz = (uint32_t)(lrow & 7) << 4;

        // register double-buffered 16-deep kk pipeline
        uint32_t a0[2][4], a1[2][4], w[2][4];
        {
            uint32_t cc = (uint32_t)lcb;
            uint32_t ad = aRow + (((cc & 7) << 4) ^ swz) + (cc & 24) * 16;
            ldmx4(a0[0], ad);
            ldmx4(a1[0], ad + 16 * 512);
            w[0][0] = lds32(q0);
            w[0][1] = lds32(q0 + 512);
            w[0][2] = lds32(q1);
            w[0][3] = lds32(q1 + 512);
        }
        #pragma unroll
        for (int kk = 0; kk < 16; kk++) {
            int cur = kk & 1, nx = cur ^ 1;
            if (kk < 15) {
                uint32_t cc = (uint32_t)((kk + 1) * 2 + lcb);
                uint32_t ad = aRow + (((cc & 7) << 4) ^ swz) + (cc & 24) * 16;
                ldmx4(a0[nx], ad);
                ldmx4(a1[nx], ad + 16 * 512);
                w[nx][0] = lds32(q0 + (kk + 1) * 1024);
                w[nx][1] = lds32(q0 + (kk + 1) * 1024 + 512);
                w[nx][2] = lds32(q1 + (kk + 1) * 1024);
                w[nx][3] = lds32(q1 + (kk + 1) * 1024 + 512);
            }
            uint32_t b00 = ((w[cur][0] >> sh4) & 0x000F000Fu) | 0x64006400u;
            uint32_t b01 = ((w[cur][1] >> sh4) & 0x000F000Fu) | 0x64006400u;
            uint32_t b10 = ((w[cur][2] >> sh4) & 0x000F000Fu) | 0x64006400u;
            uint32_t b11 = ((w[cur][3] >> sh4) & 0x000F000Fu) | 0x64006400u;

            mma16816(acc[0][0], a0[cur], b00, b01);
            mma16816(acc[1][0], a1[cur], b00, b01);
            mma16816(acc[0][1], a0[cur], b10, b11);
            mma16816(acc[1][1], a1[cur], b10, b11);
        }

        if (++slot >= STAGES) slot = 0;

        // flush at segment end (tile boundary or range end)
        bool last = (u + 1 == u1);
        if (last || ((u + 1) >> 4) != seg_nt) {
            int n0 = seg_nt * TILE_N;
            #pragma unroll
            for (int mt = 0; mt < 2; mt++) {
                #pragma unroll
                for (int j = 0; j < 2; j++) {
                    int ncl = wid * 16 + j * 8 + j4 * 2;
                    int col = n0 + ncl;
                    float s0 = __ldg(scales + col), s1 = __ldg(scales + col + 1);
                    int r0 = mt * 16 + nrow;
                    int r1 = r0 + 8;
                    float v00 = s0 * acc[mt][j][0];
                    float v01 = s1 * acc[mt][j][1];
                    float v10 = s0 * acc[mt][j][2];
                    float v11 = s1 * acc[mt][j][3];
                    if (seg_first) {
                        float c0 = fmaf(1024.f, s0, __ldg(zeros + col));
                        float c1 = fmaf(1024.f, s1, __ldg(zeros + col + 1));
                        float b0 = __ldg(bias + col);
                        float b1 = __ldg(bias + col + 1);
                        float S0 = S_sm[r0], S1 = S_sm[r1];
                        v00 += b0 - S0 * c0;
                        v01 += b1 - S0 * c1;
                        v10 += b0 - S1 * c0;
                        v11 += b1 - S1 * c1;
                    }
                    atomicAdd(out + (size_t)r0 * NTOT + col,     v00);
                    atomicAdd(out + (size_t)r0 * NTOT + col + 1, v01);
                    atomicAdd(out + (size_t)r1 * NTOT + col,     v10);
                    atomicAdd(out + (size_t)r1 * NTOT + col + 1, v11);
                    acc[mt][j][0] = acc[mt][j][1] = acc[mt][j][2] = acc[mt][j][3] = 0.f;
                }
            }
            if (!last) {
                seg_nt = (u + 1) >> 4;
                seg_first = true;        // boundary segments start at chunk 0
            }
        }
    }
}

// ---------------------------------------------------------------------------
extern "C" void kernel_launch(void* const* d_in, const int* in_sizes, int n_in,
                              void* d_out, int out_size) {
    const float* x      = (const float*)d_in[0];
    const int*   qw     = (const int*)d_in[1];
    const float* scales = (const float*)d_in[2];
    const float* zeros  = (const float*)d_in[3];
    const float* bias   = (const float*)d_in[4];
    float* out = (float*)d_out;

    cudaFuncSetAttribute(gemm_kernel, cudaFuncAttributeMaxDynamicSharedMemorySize, SMEM_TOTAL);

    prep_kernel<<<128, 128>>>(x, out);
    gemm_kernel<<<GRID, THREADS, SMEM_TOTAL>>>(qw, scales, zeros, bias, out);
}